// round 16
// baseline (speedup 1.0000x reference)
#include <cuda_runtime.h>
#include <math.h>

#define HBG 512
#define WBG 512
#define HW  (HBG * WBG)
#define IH  128
#define IW  128
#define NC  64
#define NINST 8
#define BIGV 100000.0f

typedef unsigned long long ull;

// Scratch (device globals — allocation-free rule).
__device__ float  g_bg1[NC * HW];             // bg L1 out; later htmp slabs
__device__ float  g_bg2[NC * HW];             // bg L2 out
__device__ float  g_i1[NINST * NC * IH * IW]; // inst L1 out
__device__ float  g_i2[NINST * NC * IH * IW]; // inst L2 out
__device__ float  g_imask[NINST * IH * IW];
__device__ float  g_bgmask[HW];
__device__ float  g_wf[9 * HW];
__device__ float2 g_wpk[4 * 64 * 32 * 10];    // [set][ci][cp][k]

#define FMA2(d, a, b) asm("fma.rn.f32x2 %0, %1, %2, %3;" : "=l"(d) : "l"(a), "l"(b), "l"(d))

__device__ __forceinline__ ull packf2(float a, float b) {
    return (ull)__float_as_uint(a) | ((ull)__float_as_uint(b) << 32);
}

// cp.async helpers
__device__ __forceinline__ void cpa4(unsigned dst, const void* src, bool ok) {
    if (ok)
        asm volatile("cp.async.ca.shared.global [%0], [%1], 4;" :: "r"(dst), "l"(src));
    else
        asm volatile("cp.async.ca.shared.global [%0], [%1], 4, 0;" :: "r"(dst), "l"(src));
}
__device__ __forceinline__ void cpa16(unsigned dst, const void* src) {
    asm volatile("cp.async.ca.shared.global [%0], [%1], 16;" :: "r"(dst), "l"(src));
}

__device__ __constant__ int cL[8]  = {0, 64, 128, 300, 64, 200, 32, 256};
__device__ __constant__ int cT[8]  = {0, 32, 256, 300, 128, 100, 256, 320};
__device__ __constant__ int cBW[8] = {256, 192, 320, 128, 384, 256, 160, 224};
__device__ __constant__ int cBH[8] = {256, 320, 192, 128, 256, 384, 224, 160};
__device__ __constant__ int cHOFF[8] = {0, 2097152, 3670016, 6291456,
                                        7340032, 10485760, 12582912, 13893632};

// ---------------------------------------------------------------------------
// Pre-pack all 4 weight sets in one launch. blockIdx.y = set.
// ---------------------------------------------------------------------------
__global__ void prepack4(const float* __restrict__ w0, const float* __restrict__ w1,
                         const float* __restrict__ w2, const float* __restrict__ w3)
{
    int idx = blockIdx.x * 256 + threadIdx.x;
    if (idx >= 64 * 32 * 10) return;
    int set = blockIdx.y;
    const float* w = (set == 0) ? w0 : (set == 1) ? w1 : (set == 2) ? w2 : w3;
    int k  = idx % 10;
    int cp = (idx / 10) % 32;
    int ci = idx / 320;
    float2 v = make_float2(0.f, 0.f);
    if (k < 9) {
        v.x = w[((2 * cp)     * 64 + ci) * 9 + k];
        v.y = w[((2 * cp + 1) * 64 + ci) * 9 + k];
    }
    g_wpk[set * 20480 + idx] = v;
}

// ---------------------------------------------------------------------------
// conv 3x3 SAME 64->64 (+bias, ReLU) — f32x2, cp.async 3-buffer, 3 CTAs/SM.
// bg tiles with tX==31 (x 496-511) are dead (box union ends at x=479): skip.
// ---------------------------------------------------------------------------
__global__ __launch_bounds__(256, 3)
void conv64v(const float* __restrict__ inI, const float* __restrict__ inBg,
             float* __restrict__ outI, float* __restrict__ outBg,
             const float* __restrict__ biasI, const float* __restrict__ biasBg,
             int wsI, int wsBg)
{
    __shared__ __align__(16) float  s_in[3][2448];   // 4 ci x 34x18 halo, raw
    __shared__ __align__(16) float4 s_w4[3][160];    // [ci][cp8][k pad10] as f4

    const int b = blockIdx.x;
    int W, tX, tY, batch, qz, wset;
    const float* in; float* out; const float* bias;
    if (b < 2048) {
        W = 512; qz = b >> 9;
        int t = b & 511; tX = t & 31; tY = t >> 5; batch = 0;
        if (tX == 31) return;                    // dead strip x>=496
        in = inBg; out = outBg; bias = biasBg; wset = wsBg;
    } else {
        int b2 = b - 2048;
        W = 128; qz = b2 >> 8;
        int r = b2 & 255; batch = r >> 5;
        int t = r & 31; tX = t & 7; tY = t >> 3;
        in = inI; out = outI; bias = biasI; wset = wsI;
    }
    const int H = W;
    const int tid = threadIdx.x;
    const int px  = tid & 15;
    const int pyh = tid >> 4;
    const int ox = (tX << 4) + px;
    const int oy0 = (tY << 5) + (pyh << 1);
    const int chanStride = H * W;
    const float* inB = in + batch * NC * chanStride;
    const float4* wsrc = reinterpret_cast<const float4*>(g_wpk) + wset * 10240;

    ull accA[8], accB[8];
#pragma unroll
    for (int i = 0; i < 8; i++) { accA[i] = 0ull; accB[i] = 0ull; }

    auto issue_chunk = [&](int cc, int bf) {
        unsigned sbase = (unsigned)__cvta_generic_to_shared(&s_in[bf][0]);
#pragma unroll
        for (int k = 0; k < 10; k++) {
            int idx = tid + k * 256;
            if (idx < 2448) {
                int ci = idx / 612;
                int r  = idx - ci * 612;
                int ry = r / 18, rx = r - ry * 18;
                int gy = (tY << 5) + ry - 1;
                int gx = (tX << 4) + rx - 1;
                bool ok = (unsigned)gy < (unsigned)H && (unsigned)gx < (unsigned)W;
                const float* src = inB + (cc * 4 + ci) * chanStride +
                                   (ok ? gy * W + gx : 0);
                cpa4(sbase + idx * 4, src, ok);
            }
        }
        if (tid < 160) {
            unsigned wdst = (unsigned)__cvta_generic_to_shared(&s_w4[bf][tid]);
            int ci = tid / 40;
            int r  = tid - ci * 40;
            cpa16(wdst, wsrc + (cc * 4 + ci) * 160 + qz * 40 + r);
        }
        asm volatile("cp.async.commit_group;" ::: "memory");
    };

    issue_chunk(0, 0);

#pragma unroll 1
    for (int cc = 0; cc < 16; cc++) {
        const int cur = cc % 3;
        if (cc < 15) issue_chunk(cc + 1, (cc + 1) % 3);
        if (cc < 15) asm volatile("cp.async.wait_group 1;" ::: "memory");
        else         asm volatile("cp.async.wait_group 0;" ::: "memory");
        __syncthreads();

#pragma unroll
        for (int ci = 0; ci < 4; ci++) {
            const float* si = s_in[cur] + ci * 612 + (pyh << 1) * 18 + px;
            float p0  = si[0],  p1  = si[1],  p2  = si[2];
            float p3  = si[18], p4  = si[19], p5  = si[20];
            float p6  = si[36], p7  = si[37], p8  = si[38];
            float p9  = si[54], p10 = si[55], p11 = si[56];
            ull t0  = packf2(p0,  p0),  t1  = packf2(p1,  p1),  t2  = packf2(p2,  p2);
            ull t3  = packf2(p3,  p3),  t4  = packf2(p4,  p4),  t5  = packf2(p5,  p5);
            ull t6  = packf2(p6,  p6),  t7  = packf2(p7,  p7),  t8  = packf2(p8,  p8);
            ull t9  = packf2(p9,  p9),  t10 = packf2(p10, p10), t11 = packf2(p11, p11);
            const ulonglong2* wrow =
                reinterpret_cast<const ulonglong2*>(&s_w4[cur][ci * 40]);
#pragma unroll
            for (int cp = 0; cp < 8; cp++) {
                ulonglong2 wa = wrow[cp * 5 + 0];
                ulonglong2 wb = wrow[cp * 5 + 1];
                ulonglong2 wc = wrow[cp * 5 + 2];
                ulonglong2 wd = wrow[cp * 5 + 3];
                ull we = reinterpret_cast<const ull*>(wrow)[cp * 10 + 8];
                FMA2(accA[cp], t0, wa.x);
                FMA2(accA[cp], t1, wa.y);
                FMA2(accA[cp], t2, wb.x);
                FMA2(accA[cp], t3, wb.y);
                FMA2(accA[cp], t4, wc.x);
                FMA2(accA[cp], t5, wc.y);
                FMA2(accA[cp], t6, wd.x);
                FMA2(accA[cp], t7, wd.y);
                FMA2(accA[cp], t8, we);
                FMA2(accB[cp], t3, wa.x);
                FMA2(accB[cp], t4, wa.y);
                FMA2(accB[cp], t5, wb.x);
                FMA2(accB[cp], t6, wb.y);
                FMA2(accB[cp], t7, wc.x);
                FMA2(accB[cp], t8, wc.y);
                FMA2(accB[cp], t9, wd.x);
                FMA2(accB[cp], t10, wd.y);
                FMA2(accB[cp], t11, we);
            }
        }
    }

    float* outB = out + batch * NC * chanStride + oy0 * W + ox;
#pragma unroll
    for (int cp = 0; cp < 8; cp++) {
        int gp = qz * 8 + cp;
        float b0 = bias[2 * gp], b1 = bias[2 * gp + 1];
        unsigned a_lo = (unsigned)(accA[cp] & 0xffffffffull);
        unsigned a_hi = (unsigned)(accA[cp] >> 32);
        unsigned b_lo = (unsigned)(accB[cp] & 0xffffffffull);
        unsigned b_hi = (unsigned)(accB[cp] >> 32);
        float v00 = __uint_as_float(a_lo) + b0;
        float v01 = __uint_as_float(a_hi) + b1;
        float v10 = __uint_as_float(b_lo) + b0;
        float v11 = __uint_as_float(b_hi) + b1;
        float* p0 = outB + (2 * gp) * chanStride;
        float* p1 = outB + (2 * gp + 1) * chanStride;
        p0[0] = v00 > 0.f ? v00 : 0.f;
        p1[0] = v01 > 0.f ? v01 : 0.f;
        p0[W] = v10 > 0.f ? v10 : 0.f;
        p1[W] = v11 > 0.f ? v11 : 0.f;
    }
}

// ---------------------------------------------------------------------------
// Mask head conv 3x3 64->1 — dual-copy smem (shifted) eliminates pack MOVs:
// every overlapping pixel pair is an aligned LDS.64. Weights pre-dup'd (w,w).
// ---------------------------------------------------------------------------
__global__ __launch_bounds__(256)
void conv1g(const float* __restrict__ inI, const float* __restrict__ inBg,
            const float* __restrict__ wI, const float* __restrict__ bI,
            const float* __restrict__ wBg, const float* __restrict__ bBg)
{
    __shared__ __align__(16) float sA[4 * 18 * 68];   // [ci][row18][col pad68]
    __shared__ __align__(16) float sB[4 * 18 * 68];   // shifted by 1 col
    __shared__ __align__(16) ull   swp[576];          // (w,w) pairs

    const int b = blockIdx.x;
    int W, X0, Y0, batch;
    const float* in; const float* wgt; const float* bptr; float* out;
    if (b < 256) {
        W = 512; X0 = (b & 7) * 64; Y0 = (b >> 3) * 16; batch = 0;
        in = inBg; wgt = wBg; bptr = bBg; out = g_bgmask;
    } else {
        int b2 = b - 256;
        W = 128; batch = b2 >> 4;
        int t = b2 & 15; X0 = (t & 1) * 64; Y0 = (t >> 1) * 16;
        in = inI; wgt = wI; bptr = bI; out = g_imask;
    }
    const int H = W;
    const int tid = threadIdx.x;
    const int xg = tid & 15;
    const int py = tid >> 4;
    const int chs = H * W;
    const float* inB = in + batch * NC * chs;

    for (int k = tid; k < 576; k += 256) {
        float w = wgt[k];
        swp[k] = packf2(w, w);
    }

    ull acc0 = 0ull, acc1 = 0ull;

    for (int cc = 0; cc < 16; cc++) {
        for (int idx = tid; idx < 4 * 18 * 66; idx += 256) {
            int ci = idx / 1188;
            int r  = idx - ci * 1188;
            int row = r / 66, col = r - row * 66;
            int gy = Y0 - 1 + row, gx = X0 - 1 + col;
            float v = 0.f;
            if ((unsigned)gy < (unsigned)H && (unsigned)gx < (unsigned)W)
                v = inB[(cc * 4 + ci) * chs + gy * W + gx];
            int o = ci * 1224 + row * 68;
            sA[o + col] = v;
            if (col > 0) sB[o + col - 1] = v;
        }
        __syncthreads();

#pragma unroll
        for (int ci = 0; ci < 4; ci++) {
            const ull* w9 = swp + (cc * 4 + ci) * 9;
#pragma unroll
            for (int r = 0; r < 3; r++) {
                ull w0 = w9[r * 3 + 0];
                ull w1 = w9[r * 3 + 1];
                ull w2 = w9[r * 3 + 2];
                int ro = ci * 1224 + (py + r) * 68 + xg * 4;
                ull a0 = *reinterpret_cast<const ull*>(sA + ro);       // d0,d1
                ull a2 = *reinterpret_cast<const ull*>(sA + ro + 2);   // d2,d3
                ull a4 = *reinterpret_cast<const ull*>(sA + ro + 4);   // d4,d5
                ull b0 = *reinterpret_cast<const ull*>(sB + ro);       // d1,d2
                ull b2 = *reinterpret_cast<const ull*>(sB + ro + 2);   // d3,d4
                FMA2(acc0, a0, w0);
                FMA2(acc1, a2, w0);
                FMA2(acc0, b0, w1);
                FMA2(acc1, b2, w1);
                FMA2(acc0, a2, w2);
                FMA2(acc1, a4, w2);
            }
        }
        __syncthreads();
    }

    float bv = bptr[0];
    float a0 = __uint_as_float((unsigned)(acc0 & 0xffffffffull)) + bv;
    float a1 = __uint_as_float((unsigned)(acc0 >> 32)) + bv;
    float a2 = __uint_as_float((unsigned)(acc1 & 0xffffffffull)) + bv;
    float a3 = __uint_as_float((unsigned)(acc1 >> 32)) + bv;
    float4 o = make_float4(a0 > 0.f ? a0 : 0.f, a1 > 0.f ? a1 : 0.f,
                           a2 > 0.f ? a2 : 0.f, a3 > 0.f ? a3 : 0.f);
    *reinterpret_cast<float4*>(out + batch * chs + (Y0 + py) * W + X0 + xg * 4) = o;
}

// ---------------------------------------------------------------------------
// Epilogue stage 1: softmax weight fields
// ---------------------------------------------------------------------------
__global__ __launch_bounds__(256)
void wfield_k()
{
    const int p4 = blockIdx.x * 256 + threadIdx.x;
    const int base = p4 * 4, y = base >> 9, xb = base & 511;
    float4 wv[9];
#pragma unroll
    for (int j = 0; j < 4; j++) {
        const int x = xb + j;
        float m[8]; bool uni = false;
#pragma unroll
        for (int i = 0; i < 8; i++) {
            int xl = x - cL[i], yt = y - cT[i];
            bool in_i = ((unsigned)xl < (unsigned)cBW[i]) && ((unsigned)yt < (unsigned)cBH[i]);
            uni |= in_i;
            float mi = 0.f;
            if (in_i) {
                float sx = ((float)xl + 0.5f) * (128.f / (float)cBW[i]) - 0.5f;
                float sy = ((float)yt + 0.5f) * (128.f / (float)cBH[i]) - 0.5f;
                float fxf = floorf(sx), fyf = floorf(sy);
                float fx = sx - fxf, fy = sy - fyf;
                int x0 = (int)fxf, y0 = (int)fyf;
                int x0c = x0 < 0 ? 0 : x0, x1c = (x0 + 1 > 127) ? 127 : (x0 + 1);
                int y0c = y0 < 0 ? 0 : y0, y1c = (y0 + 1 > 127) ? 127 : (y0 + 1);
                const float* mp = g_imask + i * (IH * IW);
                float v00 = mp[y0c*128+x0c], v01 = mp[y0c*128+x1c];
                float v10 = mp[y1c*128+x0c], v11 = mp[y1c*128+x1c];
                mi = (1.f-fx)*(1.f-fy)*v00 + fx*(1.f-fy)*v01 + (1.f-fx)*fy*v10 + fx*fy*v11;
            }
            m[i] = mi;
        }
        float bgv = g_bgmask[base + j] + (uni ? 0.f : BIGV);
        float mx = bgv;
#pragma unroll
        for (int i = 0; i < 8; i++) mx = fmaxf(mx, m[i]);
        float ebg = expf(bgv - mx), s = ebg, e[8];
#pragma unroll
        for (int i = 0; i < 8; i++) { e[i] = expf(m[i] - mx); s += e[i]; }
        float inv = 1.f / s;
#pragma unroll
        for (int i = 0; i < 8; i++) (&wv[i].x)[j] = e[i] * inv;
        (&wv[8].x)[j] = ebg * inv;
    }
#pragma unroll
    for (int i = 0; i < 9; i++)
        reinterpret_cast<float4*>(g_wf + i * HW)[p4] = wv[i];
}

// ---------------------------------------------------------------------------
// Epilogue stage 2: merged horizontal resize, all 8 instances.
// ---------------------------------------------------------------------------
__global__ __launch_bounds__(128)
void hresizeM(const float* __restrict__ instf)
{
    __shared__ float srow[128];
    const int bid = blockIdx.x;
    const int inst = bid >> 13;
    const int c = (bid >> 7) & 63;
    const int sy = bid & 127;
    const int tid = threadIdx.x;
    const int bw = cBW[inst];
    const float scale = 128.f / (float)bw;

    const float* src = instf + ((inst * 64 + c) * 128 + sy) * 128;
    if (tid < 32)
        reinterpret_cast<float4*>(srow)[tid] = reinterpret_cast<const float4*>(src)[tid];
    __syncthreads();
    float* dst = g_bg1 + cHOFF[inst] + (c * 128 + sy) * bw;
    for (int xg = tid; xg < (bw >> 2); xg += 128) {
        float4 o;
#pragma unroll
        for (int j = 0; j < 4; j++) {
            int x = xg * 4 + j;
            float sx = ((float)x + 0.5f) * scale - 0.5f;
            float fxf = floorf(sx), fx = sx - fxf;
            int x0 = (int)fxf;
            int x0c = x0 < 0 ? 0 : x0, x1c = (x0 + 1 > 127) ? 127 : (x0 + 1);
            (&o.x)[j] = (1.f - fx) * srow[x0c] + fx * srow[x1c];
        }
        reinterpret_cast<float4*>(dst)[xg] = o;
    }
}

// ---------------------------------------------------------------------------
// Epilogue stage 3: vertical lerp + weighted sum + bg. Channel-invariant
// geometry & softmax weights hoisted out of the channel loop.
// grid = (256 pixel-blocks, 4 channel-quarters)
// ---------------------------------------------------------------------------
__global__ __launch_bounds__(256)
void gather3R(const float* __restrict__ bgf, float* __restrict__ out)
{
    const int p4 = blockIdx.x * 256 + threadIdx.x;    // 0..65535
    const int cg = blockIdx.y;                        // channel quarter
    const int base = p4 * 4, y = base >> 9, xb = base & 511;

    float4 wi[8];
    float fy_[8], g0_[8];
    int off0[8], off1[8], cstr[8];
    bool inb[8];

#pragma unroll
    for (int i = 0; i < 8; i++) {
        int xl = xb - cL[i], yt = y - cT[i];
        bool in_i = ((unsigned)xl < (unsigned)cBW[i]) && ((unsigned)yt < (unsigned)cBH[i]);
        inb[i] = in_i;
        wi[i] = in_i ? reinterpret_cast<const float4*>(g_wf + i * HW)[p4]
                     : make_float4(0.f, 0.f, 0.f, 0.f);
        float sy = ((float)yt + 0.5f) * (128.f / (float)cBH[i]) - 0.5f;
        float fyf = floorf(sy);
        float fy = sy - fyf;
        int y0 = (int)fyf;
        int y0c = y0 < 0 ? 0 : y0, y1c = (y0 + 1 > 127) ? 127 : (y0 + 1);
        cstr[i] = 128 * cBW[i];
        int c0 = cg * 16 * cstr[i];
        off0[i] = cHOFF[i] + y0c * cBW[i] + xl + c0;
        off1[i] = cHOFF[i] + y1c * cBW[i] + xl + c0;
        fy_[i] = fy; g0_[i] = 1.f - fy;
    }
    float4 wbg = reinterpret_cast<const float4*>(g_wf + 8 * HW)[p4];

#pragma unroll 1
    for (int c = cg * 16; c < cg * 16 + 16; c++) {
        float4 bg4 = reinterpret_cast<const float4*>(bgf + (size_t)c * HW)[p4];
        float4 acc = make_float4(wbg.x * bg4.x, wbg.y * bg4.y,
                                 wbg.z * bg4.z, wbg.w * bg4.w);
#pragma unroll
        for (int i = 0; i < 8; i++) {
            if (inb[i]) {
                float4 r0 = *reinterpret_cast<const float4*>(g_bg1 + off0[i]);
                float4 r1 = *reinterpret_cast<const float4*>(g_bg1 + off1[i]);
                float g0 = g0_[i], fy = fy_[i];
                acc.x += wi[i].x * (g0 * r0.x + fy * r1.x);
                acc.y += wi[i].y * (g0 * r0.y + fy * r1.y);
                acc.z += wi[i].z * (g0 * r0.z + fy * r1.z);
                acc.w += wi[i].w * (g0 * r0.w + fy * r1.w);
                off0[i] += cstr[i];
                off1[i] += cstr[i];
            }
        }
        reinterpret_cast<float4*>(out + (size_t)c * HW)[p4] = acc;
    }
}

// ---------------------------------------------------------------------------
extern "C" void kernel_launch(void* const* d_in, const int* in_sizes, int n_in,
                              void* d_out, int out_size)
{
    const float* instf = (const float*)d_in[0];
    const float* bgf   = (const float*)d_in[1];
    const float* iw1 = (const float*)d_in[2];
    const float* ib1 = (const float*)d_in[3];
    const float* iw2 = (const float*)d_in[4];
    const float* ib2 = (const float*)d_in[5];
    const float* iw3 = (const float*)d_in[6];
    const float* ib3 = (const float*)d_in[7];
    const float* bw1 = (const float*)d_in[8];
    const float* bb1 = (const float*)d_in[9];
    const float* bw2 = (const float*)d_in[10];
    const float* bb2 = (const float*)d_in[11];
    const float* bw3 = (const float*)d_in[12];
    const float* bb3 = (const float*)d_in[13];
    float* out = (float*)d_out;

    float *ga, *gb, *gi1, *gi2;
    cudaGetSymbolAddress((void**)&ga,  g_bg1);
    cudaGetSymbolAddress((void**)&gb,  g_bg2);
    cudaGetSymbolAddress((void**)&gi1, g_i1);
    cudaGetSymbolAddress((void**)&gi2, g_i2);

    const int PP = (64 * 32 * 10 + 255) / 256;

    prepack4<<<dim3(PP, 4), 256>>>(iw1, iw2, bw1, bw2);

    // Merged conv layers, cp.async pipelined core at 3 CTAs/SM (+dead-tile skip)
    conv64v<<<3072, 256>>>(instf, bgf, gi1, ga, ib1, bb1, 0, 2);
    conv64v<<<3072, 256>>>(gi1,   ga,  gi2, gb, ib2, bb2, 1, 3);

    // Merged mask heads (dual-copy smem, pack-free)
    conv1g<<<384, 256>>>(gi2, gb, iw3, ib3, bw3, bb3);

    // Epilogue
    wfield_k<<<HW / 4 / 256, 256>>>();
    hresizeM<<<8 * 64 * 128, 128>>>(instf);
    gather3R<<<dim3(256, 4), 256>>>(bgf, out);
}

// round 17
// speedup vs baseline: 1.0737x; 1.0737x over previous
#include <cuda_runtime.h>
#include <math.h>

#define HBG 512
#define WBG 512
#define HW  (HBG * WBG)
#define IH  128
#define IW  128
#define NC  64
#define NINST 8
#define BIGV 100000.0f

typedef unsigned long long ull;

// Scratch (device globals — allocation-free rule).
__device__ float  g_bg1[NC * HW];             // bg L1 out; later htmp slabs
__device__ float  g_bg2[NC * HW];             // bg L2 out
__device__ float  g_i1[NINST * NC * IH * IW]; // inst L1 out
__device__ float  g_i2[NINST * NC * IH * IW]; // inst L2 out
__device__ float  g_imask[NINST * IH * IW];
__device__ float  g_bgmask[HW];
__device__ float  g_wf[9 * HW];
__device__ float2 g_wpk[4 * 64 * 32 * 10];    // [set][ci][cp][k]

#define FMA2(d, a, b) asm("fma.rn.f32x2 %0, %1, %2, %3;" : "=l"(d) : "l"(a), "l"(b), "l"(d))

__device__ __forceinline__ ull packf2(float a, float b) {
    return (ull)__float_as_uint(a) | ((ull)__float_as_uint(b) << 32);
}

// cp.async helpers
__device__ __forceinline__ void cpa4(unsigned dst, const void* src, bool ok) {
    if (ok)
        asm volatile("cp.async.ca.shared.global [%0], [%1], 4;" :: "r"(dst), "l"(src));
    else
        asm volatile("cp.async.ca.shared.global [%0], [%1], 4, 0;" :: "r"(dst), "l"(src));
}
__device__ __forceinline__ void cpa16(unsigned dst, const void* src) {
    asm volatile("cp.async.ca.shared.global [%0], [%1], 16;" :: "r"(dst), "l"(src));
}

__device__ __constant__ int cL[8]  = {0, 64, 128, 300, 64, 200, 32, 256};
__device__ __constant__ int cT[8]  = {0, 32, 256, 300, 128, 100, 256, 320};
__device__ __constant__ int cBW[8] = {256, 192, 320, 128, 384, 256, 160, 224};
__device__ __constant__ int cBH[8] = {256, 320, 192, 128, 256, 384, 224, 160};
__device__ __constant__ int cHOFF[8] = {0, 2097152, 3670016, 6291456,
                                        7340032, 10485760, 12582912, 13893632};

// ---------------------------------------------------------------------------
// Pre-pack all 4 weight sets in one launch. blockIdx.y = set.
// ---------------------------------------------------------------------------
__global__ void prepack4(const float* __restrict__ w0, const float* __restrict__ w1,
                         const float* __restrict__ w2, const float* __restrict__ w3)
{
    int idx = blockIdx.x * 256 + threadIdx.x;
    if (idx >= 64 * 32 * 10) return;
    int set = blockIdx.y;
    const float* w = (set == 0) ? w0 : (set == 1) ? w1 : (set == 2) ? w2 : w3;
    int k  = idx % 10;
    int cp = (idx / 10) % 32;
    int ci = idx / 320;
    float2 v = make_float2(0.f, 0.f);
    if (k < 9) {
        v.x = w[((2 * cp)     * 64 + ci) * 9 + k];
        v.y = w[((2 * cp + 1) * 64 + ci) * 9 + k];
    }
    g_wpk[set * 20480 + idx] = v;
}

// ---------------------------------------------------------------------------
// conv 3x3 SAME 64->64 (+bias, ReLU) — f32x2, cp.async 3-buffer, 3 CTAs/SM.
// bg tiles with tX==31 (x 496-511) are dead (box union ends at x=479;
// outside the union wbg == 1.0 exactly in fp32, independent of bgmask): skip.
// MERGED grid: blocks [0,2048) = bg 512x512, [2048,3072) = 8 inst 128x128.
// ---------------------------------------------------------------------------
__global__ __launch_bounds__(256, 3)
void conv64v(const float* __restrict__ inI, const float* __restrict__ inBg,
             float* __restrict__ outI, float* __restrict__ outBg,
             const float* __restrict__ biasI, const float* __restrict__ biasBg,
             int wsI, int wsBg)
{
    __shared__ __align__(16) float  s_in[3][2448];   // 4 ci x 34x18 halo, raw
    __shared__ __align__(16) float4 s_w4[3][160];    // [ci][cp8][k pad10] as f4

    const int b = blockIdx.x;
    int W, tX, tY, batch, qz, wset;
    const float* in; float* out; const float* bias;
    if (b < 2048) {
        W = 512; qz = b >> 9;
        int t = b & 511; tX = t & 31; tY = t >> 5; batch = 0;
        if (tX == 31) return;                    // dead strip x>=496
        in = inBg; out = outBg; bias = biasBg; wset = wsBg;
    } else {
        int b2 = b - 2048;
        W = 128; qz = b2 >> 8;
        int r = b2 & 255; batch = r >> 5;
        int t = r & 31; tX = t & 7; tY = t >> 3;
        in = inI; out = outI; bias = biasI; wset = wsI;
    }
    const int H = W;
    const int tid = threadIdx.x;
    const int px  = tid & 15;
    const int pyh = tid >> 4;
    const int ox = (tX << 4) + px;
    const int oy0 = (tY << 5) + (pyh << 1);
    const int chanStride = H * W;
    const float* inB = in + batch * NC * chanStride;
    const float4* wsrc = reinterpret_cast<const float4*>(g_wpk) + wset * 10240;

    ull accA[8], accB[8];
#pragma unroll
    for (int i = 0; i < 8; i++) { accA[i] = 0ull; accB[i] = 0ull; }

    auto issue_chunk = [&](int cc, int bf) {
        unsigned sbase = (unsigned)__cvta_generic_to_shared(&s_in[bf][0]);
#pragma unroll
        for (int k = 0; k < 10; k++) {
            int idx = tid + k * 256;
            if (idx < 2448) {
                int ci = idx / 612;
                int r  = idx - ci * 612;
                int ry = r / 18, rx = r - ry * 18;
                int gy = (tY << 5) + ry - 1;
                int gx = (tX << 4) + rx - 1;
                bool ok = (unsigned)gy < (unsigned)H && (unsigned)gx < (unsigned)W;
                const float* src = inB + (cc * 4 + ci) * chanStride +
                                   (ok ? gy * W + gx : 0);
                cpa4(sbase + idx * 4, src, ok);
            }
        }
        if (tid < 160) {
            unsigned wdst = (unsigned)__cvta_generic_to_shared(&s_w4[bf][tid]);
            int ci = tid / 40;
            int r  = tid - ci * 40;
            cpa16(wdst, wsrc + (cc * 4 + ci) * 160 + qz * 40 + r);
        }
        asm volatile("cp.async.commit_group;" ::: "memory");
    };

    issue_chunk(0, 0);

#pragma unroll 1
    for (int cc = 0; cc < 16; cc++) {
        const int cur = cc % 3;
        if (cc < 15) issue_chunk(cc + 1, (cc + 1) % 3);
        if (cc < 15) asm volatile("cp.async.wait_group 1;" ::: "memory");
        else         asm volatile("cp.async.wait_group 0;" ::: "memory");
        __syncthreads();

#pragma unroll
        for (int ci = 0; ci < 4; ci++) {
            const float* si = s_in[cur] + ci * 612 + (pyh << 1) * 18 + px;
            float p0  = si[0],  p1  = si[1],  p2  = si[2];
            float p3  = si[18], p4  = si[19], p5  = si[20];
            float p6  = si[36], p7  = si[37], p8  = si[38];
            float p9  = si[54], p10 = si[55], p11 = si[56];
            ull t0  = packf2(p0,  p0),  t1  = packf2(p1,  p1),  t2  = packf2(p2,  p2);
            ull t3  = packf2(p3,  p3),  t4  = packf2(p4,  p4),  t5  = packf2(p5,  p5);
            ull t6  = packf2(p6,  p6),  t7  = packf2(p7,  p7),  t8  = packf2(p8,  p8);
            ull t9  = packf2(p9,  p9),  t10 = packf2(p10, p10), t11 = packf2(p11, p11);
            const ulonglong2* wrow =
                reinterpret_cast<const ulonglong2*>(&s_w4[cur][ci * 40]);
#pragma unroll
            for (int cp = 0; cp < 8; cp++) {
                ulonglong2 wa = wrow[cp * 5 + 0];
                ulonglong2 wb = wrow[cp * 5 + 1];
                ulonglong2 wc = wrow[cp * 5 + 2];
                ulonglong2 wd = wrow[cp * 5 + 3];
                ull we = reinterpret_cast<const ull*>(wrow)[cp * 10 + 8];
                FMA2(accA[cp], t0, wa.x);
                FMA2(accA[cp], t1, wa.y);
                FMA2(accA[cp], t2, wb.x);
                FMA2(accA[cp], t3, wb.y);
                FMA2(accA[cp], t4, wc.x);
                FMA2(accA[cp], t5, wc.y);
                FMA2(accA[cp], t6, wd.x);
                FMA2(accA[cp], t7, wd.y);
                FMA2(accA[cp], t8, we);
                FMA2(accB[cp], t3, wa.x);
                FMA2(accB[cp], t4, wa.y);
                FMA2(accB[cp], t5, wb.x);
                FMA2(accB[cp], t6, wb.y);
                FMA2(accB[cp], t7, wc.x);
                FMA2(accB[cp], t8, wc.y);
                FMA2(accB[cp], t9, wd.x);
                FMA2(accB[cp], t10, wd.y);
                FMA2(accB[cp], t11, we);
            }
        }
    }

    float* outB = out + batch * NC * chanStride + oy0 * W + ox;
#pragma unroll
    for (int cp = 0; cp < 8; cp++) {
        int gp = qz * 8 + cp;
        float b0 = bias[2 * gp], b1 = bias[2 * gp + 1];
        unsigned a_lo = (unsigned)(accA[cp] & 0xffffffffull);
        unsigned a_hi = (unsigned)(accA[cp] >> 32);
        unsigned b_lo = (unsigned)(accB[cp] & 0xffffffffull);
        unsigned b_hi = (unsigned)(accB[cp] >> 32);
        float v00 = __uint_as_float(a_lo) + b0;
        float v01 = __uint_as_float(a_hi) + b1;
        float v10 = __uint_as_float(b_lo) + b0;
        float v11 = __uint_as_float(b_hi) + b1;
        float* p0 = outB + (2 * gp) * chanStride;
        float* p1 = outB + (2 * gp + 1) * chanStride;
        p0[0] = v00 > 0.f ? v00 : 0.f;
        p1[0] = v01 > 0.f ? v01 : 0.f;
        p0[W] = v10 > 0.f ? v10 : 0.f;
        p1[W] = v11 > 0.f ? v11 : 0.f;
    }
}

// ---------------------------------------------------------------------------
// Mask head conv 3x3 64->1 (+bias, ReLU) — f32x2 pixel-pair, 384 blocks.
// (R15 version — known good, 77us)
// ---------------------------------------------------------------------------
__global__ __launch_bounds__(256)
void conv1f(const float* __restrict__ inI, const float* __restrict__ inBg,
            const float* __restrict__ wI, const float* __restrict__ bI,
            const float* __restrict__ wBg, const float* __restrict__ bBg)
{
    __shared__ float s_in[4 * 18 * 68];
    __shared__ float sw[576];

    const int b = blockIdx.x;
    int W, X0, Y0, batch;
    const float* in; const float* wgt; const float* bptr; float* out;
    if (b < 256) {
        W = 512; X0 = (b & 7) * 64; Y0 = (b >> 3) * 16; batch = 0;
        in = inBg; wgt = wBg; bptr = bBg; out = g_bgmask;
    } else {
        int b2 = b - 256;
        W = 128; batch = b2 >> 4;
        int t = b2 & 15; X0 = (t & 1) * 64; Y0 = (t >> 1) * 16;
        in = inI; wgt = wI; bptr = bI; out = g_imask;
    }
    const int H = W;
    const int tid = threadIdx.x;
    const int xg = tid & 15;
    const int py = tid >> 4;
    const int chs = H * W;
    const float* inB = in + batch * NC * chs;

    for (int idx = tid; idx < 576; idx += 256) sw[idx] = wgt[idx];

    ull acc0 = 0ull, acc1 = 0ull;

    for (int cc = 0; cc < 16; cc++) {
        for (int idx = tid; idx < 4 * 18 * 66; idx += 256) {
            int ci = idx / 1188;
            int r  = idx - ci * 1188;
            int row = r / 66, col = r - row * 66;
            int gy = Y0 - 1 + row, gx = X0 - 1 + col;
            float v = 0.f;
            if ((unsigned)gy < (unsigned)H && (unsigned)gx < (unsigned)W)
                v = inB[(cc * 4 + ci) * chs + gy * W + gx];
            s_in[ci * 1224 + row * 68 + col] = v;
        }
        __syncthreads();

#pragma unroll
        for (int ci = 0; ci < 4; ci++) {
            const float* w9 = sw + (cc * 4 + ci) * 9;
#pragma unroll
            for (int r = 0; r < 3; r++) {
                ull w0 = packf2(w9[r*3+0], w9[r*3+0]);
                ull w1 = packf2(w9[r*3+1], w9[r*3+1]);
                ull w2 = packf2(w9[r*3+2], w9[r*3+2]);
                const float* dr = s_in + ci * 1224 + (py + r) * 68 + xg * 4;
                float d0 = dr[0], d1 = dr[1], d2 = dr[2];
                float d3 = dr[3], d4 = dr[4], d5 = dr[5];
                ull p01 = packf2(d0, d1), p23 = packf2(d2, d3);
                ull p12 = packf2(d1, d2), p34 = packf2(d3, d4);
                ull p45 = packf2(d4, d5);
                FMA2(acc0, p01, w0);
                FMA2(acc1, p23, w0);
                FMA2(acc0, p12, w1);
                FMA2(acc1, p34, w1);
                FMA2(acc0, p23, w2);
                FMA2(acc1, p45, w2);
            }
        }
        __syncthreads();
    }

    float bv = bptr[0];
    float a0 = __uint_as_float((unsigned)(acc0 & 0xffffffffull)) + bv;
    float a1 = __uint_as_float((unsigned)(acc0 >> 32)) + bv;
    float a2 = __uint_as_float((unsigned)(acc1 & 0xffffffffull)) + bv;
    float a3 = __uint_as_float((unsigned)(acc1 >> 32)) + bv;
    float4 o = make_float4(a0 > 0.f ? a0 : 0.f, a1 > 0.f ? a1 : 0.f,
                           a2 > 0.f ? a2 : 0.f, a3 > 0.f ? a3 : 0.f);
    *reinterpret_cast<float4*>(out + batch * chs + (Y0 + py) * W + X0 + xg * 4) = o;
}

// ---------------------------------------------------------------------------
// Epilogue stage 1: softmax weight fields
// ---------------------------------------------------------------------------
__global__ __launch_bounds__(256)
void wfield_k()
{
    const int p4 = blockIdx.x * 256 + threadIdx.x;
    const int base = p4 * 4, y = base >> 9, xb = base & 511;
    float4 wv[9];
#pragma unroll
    for (int j = 0; j < 4; j++) {
        const int x = xb + j;
        float m[8]; bool uni = false;
#pragma unroll
        for (int i = 0; i < 8; i++) {
            int xl = x - cL[i], yt = y - cT[i];
            bool in_i = ((unsigned)xl < (unsigned)cBW[i]) && ((unsigned)yt < (unsigned)cBH[i]);
            uni |= in_i;
            float mi = 0.f;
            if (in_i) {
                float sx = ((float)xl + 0.5f) * (128.f / (float)cBW[i]) - 0.5f;
                float sy = ((float)yt + 0.5f) * (128.f / (float)cBH[i]) - 0.5f;
                float fxf = floorf(sx), fyf = floorf(sy);
                float fx = sx - fxf, fy = sy - fyf;
                int x0 = (int)fxf, y0 = (int)fyf;
                int x0c = x0 < 0 ? 0 : x0, x1c = (x0 + 1 > 127) ? 127 : (x0 + 1);
                int y0c = y0 < 0 ? 0 : y0, y1c = (y0 + 1 > 127) ? 127 : (y0 + 1);
                const float* mp = g_imask + i * (IH * IW);
                float v00 = mp[y0c*128+x0c], v01 = mp[y0c*128+x1c];
                float v10 = mp[y1c*128+x0c], v11 = mp[y1c*128+x1c];
                mi = (1.f-fx)*(1.f-fy)*v00 + fx*(1.f-fy)*v01 + (1.f-fx)*fy*v10 + fx*fy*v11;
            }
            m[i] = mi;
        }
        float bgv = g_bgmask[base + j] + (uni ? 0.f : BIGV);
        float mx = bgv;
#pragma unroll
        for (int i = 0; i < 8; i++) mx = fmaxf(mx, m[i]);
        float ebg = expf(bgv - mx), s = ebg, e[8];
#pragma unroll
        for (int i = 0; i < 8; i++) { e[i] = expf(m[i] - mx); s += e[i]; }
        float inv = 1.f / s;
#pragma unroll
        for (int i = 0; i < 8; i++) (&wv[i].x)[j] = e[i] * inv;
        (&wv[8].x)[j] = ebg * inv;
    }
#pragma unroll
    for (int i = 0; i < 9; i++)
        reinterpret_cast<float4*>(g_wf + i * HW)[p4] = wv[i];
}

// ---------------------------------------------------------------------------
// Epilogue stage 2: merged horizontal resize, all 8 instances.
// ---------------------------------------------------------------------------
__global__ __launch_bounds__(128)
void hresizeM(const float* __restrict__ instf)
{
    __shared__ float srow[128];
    const int bid = blockIdx.x;
    const int inst = bid >> 13;
    const int c = (bid >> 7) & 63;
    const int sy = bid & 127;
    const int tid = threadIdx.x;
    const int bw = cBW[inst];
    const float scale = 128.f / (float)bw;

    const float* src = instf + ((inst * 64 + c) * 128 + sy) * 128;
    if (tid < 32)
        reinterpret_cast<float4*>(srow)[tid] = reinterpret_cast<const float4*>(src)[tid];
    __syncthreads();
    float* dst = g_bg1 + cHOFF[inst] + (c * 128 + sy) * bw;
    for (int xg = tid; xg < (bw >> 2); xg += 128) {
        float4 o;
#pragma unroll
        for (int j = 0; j < 4; j++) {
            int x = xg * 4 + j;
            float sx = ((float)x + 0.5f) * scale - 0.5f;
            float fxf = floorf(sx), fx = sx - fxf;
            int x0 = (int)fxf;
            int x0c = x0 < 0 ? 0 : x0, x1c = (x0 + 1 > 127) ? 127 : (x0 + 1);
            (&o.x)[j] = (1.f - fx) * srow[x0c] + fx * srow[x1c];
        }
        reinterpret_cast<float4*>(dst)[xg] = o;
    }
}

// ---------------------------------------------------------------------------
// Epilogue stage 3: vertical lerp + weighted sum + bg (R15 version)
// ---------------------------------------------------------------------------
__global__ __launch_bounds__(256)
void gather3(const float* __restrict__ bgf, float* __restrict__ out)
{
    const int gid = blockIdx.x * 256 + threadIdx.x;
    const int c = gid >> 16, p4 = gid & 65535;
    const int base = p4 * 4, y = base >> 9, xb = base & 511;
    float4 bg4  = reinterpret_cast<const float4*>(bgf + c * HW)[p4];
    float4 wbg4 = reinterpret_cast<const float4*>(g_wf + 8 * HW)[p4];
    float4 acc = make_float4(wbg4.x*bg4.x, wbg4.y*bg4.y, wbg4.z*bg4.z, wbg4.w*bg4.w);
#pragma unroll
    for (int i = 0; i < 8; i++) {
        int xl = xb - cL[i], yt = y - cT[i];
        if (((unsigned)xl < (unsigned)cBW[i]) && ((unsigned)yt < (unsigned)cBH[i])) {
            float4 wi4 = reinterpret_cast<const float4*>(g_wf + i * HW)[p4];
            float sy = ((float)yt + 0.5f) * (128.f / (float)cBH[i]) - 0.5f;
            float fyf = floorf(sy), fy = sy - fyf;
            int y0 = (int)fyf;
            int y0c = y0 < 0 ? 0 : y0, y1c = (y0 + 1 > 127) ? 127 : (y0 + 1);
            const float* hb = g_bg1 + cHOFF[i] + c * 128 * cBW[i];
            float4 r0 = *reinterpret_cast<const float4*>(hb + y0c * cBW[i] + xl);
            float4 r1 = *reinterpret_cast<const float4*>(hb + y1c * cBW[i] + xl);
            float g0 = 1.f - fy;
            acc.x += wi4.x * (g0*r0.x + fy*r1.x);
            acc.y += wi4.y * (g0*r0.y + fy*r1.y);
            acc.z += wi4.z * (g0*r0.z + fy*r1.z);
            acc.w += wi4.w * (g0*r0.w + fy*r1.w);
        }
    }
    reinterpret_cast<float4*>(out + c * HW)[p4] = acc;
}

// ---------------------------------------------------------------------------
extern "C" void kernel_launch(void* const* d_in, const int* in_sizes, int n_in,
                              void* d_out, int out_size)
{
    const float* instf = (const float*)d_in[0];
    const float* bgf   = (const float*)d_in[1];
    const float* iw1 = (const float*)d_in[2];
    const float* ib1 = (const float*)d_in[3];
    const float* iw2 = (const float*)d_in[4];
    const float* ib2 = (const float*)d_in[5];
    const float* iw3 = (const float*)d_in[6];
    const float* ib3 = (const float*)d_in[7];
    const float* bw1 = (const float*)d_in[8];
    const float* bb1 = (const float*)d_in[9];
    const float* bw2 = (const float*)d_in[10];
    const float* bb2 = (const float*)d_in[11];
    const float* bw3 = (const float*)d_in[12];
    const float* bb3 = (const float*)d_in[13];
    float* out = (float*)d_out;

    float *ga, *gb, *gi1, *gi2;
    cudaGetSymbolAddress((void**)&ga,  g_bg1);
    cudaGetSymbolAddress((void**)&gb,  g_bg2);
    cudaGetSymbolAddress((void**)&gi1, g_i1);
    cudaGetSymbolAddress((void**)&gi2, g_i2);

    const int PP = (64 * 32 * 10 + 255) / 256;

    prepack4<<<dim3(PP, 4), 256>>>(iw1, iw2, bw1, bw2);

    // Merged conv layers, cp.async pipelined core at 3 CTAs/SM (+dead-strip skip)
    conv64v<<<3072, 256>>>(instf, bgf, gi1, ga, ib1, bb1, 0, 2);
    conv64v<<<3072, 256>>>(gi1,   ga,  gi2, gb, ib2, bb2, 1, 3);

    // Merged pixel-packed mask heads (R15 version)
    conv1f<<<384, 256>>>(gi2, gb, iw3, ib3, bw3, bb3);

    // Epilogue (R15 versions)
    wfield_k<<<HW / 4 / 256, 256>>>();
    hresizeM<<<8 * 64 * 128, 128>>>(instf);
    gather3<<<64 * (HW / 4) / 256, 256>>>(bgf, out);
}